// round 16
// baseline (speedup 1.0000x reference)
#include <cuda_runtime.h>
#include <cuda_fp16.h>
#include <cstdint>

// ShiftConv: shift -> 1x1 conv (GEMM M=50176,N=512,K=512) -> BN -> ReLU.
// Round 16: GEMM byte-identical to R12/R15 (83us, mma.sync ceiling; tcgen05
// blocked by the harness's sm_103 PTX target). Prepass polish:
//  - x reads via __ldcs (single-use; keep L2 for g_Ah, re-read 4x by GEMM)
//  - W convert vectorized: float4 in / uint2 out, 1/4 the blocks.

#define HDIM 28
#define HW   784
#define CCH  512
#define EPSV 1e-5f

#define MMA_F16(C, A, B) \
  asm volatile("mma.sync.aligned.m16n8k16.row.col.f32.f16.f16.f32 " \
    "{%0,%1,%2,%3}, {%4,%5,%6,%7}, {%8,%9}, {%0,%1,%2,%3};" \
    : "+f"((C)[0]), "+f"((C)[1]), "+f"((C)[2]), "+f"((C)[3]) \
    : "r"((A)[0]), "r"((A)[1]), "r"((A)[2]), "r"((A)[3]), \
      "r"((B)[0]), "r"((B)[1]))

#define LDSM4(R0, R1, R2, R3, addr) \
  asm volatile("ldmatrix.sync.aligned.m8n8.x4.shared.b16 {%0,%1,%2,%3}, [%4];" \
    : "=r"(R0), "=r"(R1), "=r"(R2), "=r"(R3) : "r"(addr))

#define CP16(dst, src) \
  asm volatile("cp.async.cg.shared.global [%0], [%1], 16;" :: "r"(dst), "l"(src))
#define CPCOMMIT() asm volatile("cp.async.commit_group;" ::: "memory")
#define CPWAIT(n)  asm volatile("cp.async.wait_group %0;" :: "n"(n) : "memory")

// K-chunk 64; smem row stride 64 real + 8 pad fp16 (144B, 16B aligned)
#define KC  64
#define KST 72
#define NSTAGE 3
#define MAT_BYTES (128 * KST * 2)          // 18432
#define A_OFF 0
#define B_OFF MAT_BYTES
#define STAGE_BYTES (2 * MAT_BYTES)        // 36864
#define SMEM_TOTAL (NSTAGE * STAGE_BYTES)  // 110592

__device__ __half g_Wh[CCH * CCH];
__device__ __half g_Ah[(size_t)50176 * CCH];   // shifted x, fp16, [p][c]

__device__ __forceinline__ uint32_t smem_u32(const void* p) {
    uint32_t a;
    asm("{ .reg .u64 t; cvta.to.shared.u64 t, %1; cvt.u32.u64 %0, t; }"
        : "=r"(a) : "l"(p));
    return a;
}

// Merged prepass. Blocks [0,256): W fp32->fp16 convert (float4 / uint2).
// Blocks [256, 256+784*8): shift-gather + transpose + fp16 convert of x.
__global__ __launch_bounds__(256)
void prepass_kernel(const float* __restrict__ x, const float* __restrict__ Wm) {
    __shared__ float tile[64][65];
    __shared__ int soff[64];
    const int tid = threadIdx.x;
    const int bid = blockIdx.x;

    if (bid < 256) {
        int i = (bid * 256 + tid) * 4;
        float4 v = *(const float4*)&Wm[i];
        __half2 h0 = __floats2half2_rn(v.x, v.y);
        __half2 h1 = __floats2half2_rn(v.z, v.w);
        *(uint2*)&g_Wh[i] = make_uint2(*(uint32_t*)&h0, *(uint32_t*)&h1);
        return;
    }

    const int b2 = bid - 256;
    const int p0 = (b2 >> 3) * 64;
    const int c0 = (b2 & 7) * 64;
    const int g  = c0 >> 7;

    if (tid < 64) {
        int pg = p0 + tid;
        int b  = pg / HW;
        int hw = pg - b * HW;
        int h  = hw / HDIM;
        int w  = hw - h * HDIM;
        int hs = h, ws = w;
        if      (g == 0) hs = (h + 1) % HDIM;
        else if (g == 1) hs = (h + HDIM - 1) % HDIM;
        else if (g == 2) ws = (w + 1) % HDIM;
        else             ws = (w + HDIM - 1) % HDIM;
        soff[tid] = b * (CCH * HW) + hs * HDIM + ws;
    }
    __syncthreads();
    #pragma unroll
    for (int it = 0; it < 16; it++) {       // read coalesced over p, evict-first
        int lin = tid + it * 256;
        int c = lin >> 6, p = lin & 63;
        tile[c][p] = __ldcs(&x[(size_t)(c0 + c) * HW + soff[p]]);
    }
    __syncthreads();
    // write phase: one 8-channel octet per thread per iter, STG.128;
    // warp lanes span 8 octets x 4 p -> 4 fully-coalesced 128B lines.
    #pragma unroll
    for (int it = 0; it < 2; it++) {
        int lin = tid + it * 256;           // 0..511
        int oct = lin & 7;
        int p   = lin >> 3;
        int c   = oct * 8;
        uint32_t pk[4];
        #pragma unroll
        for (int j = 0; j < 4; j++) {
            __half2 h2 = __floats2half2_rn(tile[c + 2 * j][p],
                                           tile[c + 2 * j + 1][p]);
            pk[j] = *(uint32_t*)&h2;
        }
        *(uint4*)&g_Ah[(size_t)(p0 + p) * CCH + c0 + c] =
            make_uint4(pk[0], pk[1], pk[2], pk[3]);
    }
}

__global__ __launch_bounds__(256, 2)
void shiftconv_gemm(const float* __restrict__ gamma,
                    const float* __restrict__ beta,
                    const float* __restrict__ rmean,
                    const float* __restrict__ rvar,
                    float* __restrict__ out)
{
    extern __shared__ char dsm[];
    __shared__ float ssc[128], ssh[128];

    const int tid  = threadIdx.x;
    const int lane = tid & 31;
    const int wid  = tid >> 5;
    const int wm   = wid & 3;
    const int wn   = wid >> 2;
    const int g8   = lane >> 2;
    const int tig2 = (lane & 3) * 2;
    const int q    = lane >> 3;        // ldmatrix quad
    const int r8   = lane & 7;         // ldmatrix row within matrix

    const int pblock = blockIdx.x * 128;
    const int oblock = blockIdx.y * 128;

    if (tid < 128) {
        int o = oblock + tid;
        float sc = gamma[o] * rsqrtf(rvar[o] + EPSV);
        ssc[tid] = sc;
        ssh[tid] = beta[o] - rmean[o] * sc;
    }

    const uint32_t sdyn = smem_u32(dsm);

    uint32_t aoff[2];
    #pragma unroll
    for (int mt = 0; mt < 2; mt++)
        aoff[mt] = (uint32_t)(((wm * 32 + mt * 16 + (q & 1) * 8 + r8) * KST
                               + (q >> 1) * 8) * 2) + A_OFF;
    uint32_t boff[4];
    #pragma unroll
    for (int np = 0; np < 4; np++)
        boff[np] = (uint32_t)(((wn * 64 + np * 16 + (q >> 1) * 8 + r8) * KST
                               + (q & 1) * 8) * 2) + B_OFF;

    auto load_stage = [&](int ch) {
        int kc = ch * KC;
        uint32_t st = sdyn + (ch % NSTAGE) * STAGE_BYTES;
        #pragma unroll
        for (int it = 0; it < 4; it++) {
            int lin = tid + it * 256;
            int r = lin >> 3;
            int j = lin & 7;
            uint32_t d = st + r * (KST * 2) + j * 16;
            CP16(d + A_OFF, &g_Ah[(size_t)(pblock + r) * CCH + kc + j * 8]);
            CP16(d + B_OFF, &g_Wh[(size_t)(oblock + r) * CCH + kc + j * 8]);
        }
        CPCOMMIT();
    };

    float acc[2][8][4];
    #pragma unroll
    for (int mt = 0; mt < 2; mt++)
        #pragma unroll
        for (int nt = 0; nt < 8; nt++)
            #pragma unroll
            for (int rr = 0; rr < 4; rr++) acc[mt][nt][rr] = 0.0f;

    load_stage(0);
    load_stage(1);

    #pragma unroll
    for (int ch = 0; ch < 8; ch++) {
        if (ch < 7) CPWAIT(1);
        else        CPWAIT(0);
        __syncthreads();   // compute(ch-1) fully done -> buffer (ch-1)%3 free

        if (ch < 6) load_stage(ch + 2);   // writes buffer (ch+2)%3 == (ch-1)%3

        const uint32_t st = sdyn + (ch % NSTAGE) * STAGE_BYTES;
        #pragma unroll
        for (int kk = 0; kk < KC; kk += 16) {
            const uint32_t kb = st + kk * 2;
            uint32_t ah[2][4];
            uint32_t bh[8][2];
            LDSM4(ah[0][0], ah[0][1], ah[0][2], ah[0][3], kb + aoff[0]);
            LDSM4(ah[1][0], ah[1][1], ah[1][2], ah[1][3], kb + aoff[1]);
            LDSM4(bh[0][0], bh[0][1], bh[1][0], bh[1][1], kb + boff[0]);
            LDSM4(bh[2][0], bh[2][1], bh[3][0], bh[3][1], kb + boff[1]);

            MMA_F16(acc[0][0], ah[0], bh[0]);
            MMA_F16(acc[1][0], ah[1], bh[0]);
            MMA_F16(acc[0][1], ah[0], bh[1]);
            MMA_F16(acc[1][1], ah[1], bh[1]);
            LDSM4(bh[4][0], bh[4][1], bh[5][0], bh[5][1], kb + boff[2]);
            MMA_F16(acc[0][2], ah[0], bh[2]);
            MMA_F16(acc[1][2], ah[1], bh[2]);
            MMA_F16(acc[0][3], ah[0], bh[3]);
            MMA_F16(acc[1][3], ah[1], bh[3]);
            LDSM4(bh[6][0], bh[6][1], bh[7][0], bh[7][1], kb + boff[3]);
            MMA_F16(acc[0][4], ah[0], bh[4]);
            MMA_F16(acc[1][4], ah[1], bh[4]);
            MMA_F16(acc[0][5], ah[0], bh[5]);
            MMA_F16(acc[1][5], ah[1], bh[5]);
            MMA_F16(acc[0][6], ah[0], bh[6]);
            MMA_F16(acc[1][6], ah[1], bh[6]);
            MMA_F16(acc[0][7], ah[0], bh[7]);
            MMA_F16(acc[1][7], ah[1], bh[7]);
        }
    }

    // Epilogue: BN + ReLU.
    #pragma unroll
    for (int mt = 0; mt < 2; mt++) {
        int p0 = pblock + wm * 32 + mt * 16 + g8;
        int p1 = p0 + 8;
        int b0 = p0 / HW, hw0 = p0 - b0 * HW;
        int b1 = p1 / HW, hw1 = p1 - b1 * HW;
        #pragma unroll
        for (int nt = 0; nt < 8; nt++) {
            int oo  = wn * 64 + nt * 8 + tig2;
            float sc0 = ssc[oo],     sh0 = ssh[oo];
            float sc1 = ssc[oo + 1], sh1 = ssh[oo + 1];
            int o0 = oblock + oo;
            float* q00 = out + ((size_t)(b0 * CCH + o0)) * HW + hw0;
            float* q01 = out + ((size_t)(b0 * CCH + o0 + 1)) * HW + hw0;
            float* q10 = out + ((size_t)(b1 * CCH + o0)) * HW + hw1;
            float* q11 = out + ((size_t)(b1 * CCH + o0 + 1)) * HW + hw1;
            *q00 = fmaxf(fmaf(acc[mt][nt][0], sc0, sh0), 0.0f);
            *q01 = fmaxf(fmaf(acc[mt][nt][1], sc1, sh1), 0.0f);
            *q10 = fmaxf(fmaf(acc[mt][nt][2], sc0, sh0), 0.0f);
            *q11 = fmaxf(fmaf(acc[mt][nt][3], sc1, sh1), 0.0f);
        }
    }
}

extern "C" void kernel_launch(void* const* d_in, const int* in_sizes, int n_in,
                              void* d_out, int out_size)
{
    const float* x     = (const float*)d_in[0];
    const float* Wm    = (const float*)d_in[1];
    const float* gamma = (const float*)d_in[2];
    const float* beta  = (const float*)d_in[3];
    const float* rmean = (const float*)d_in[4];
    const float* rvar  = (const float*)d_in[5];
    float* out = (float*)d_out;

    cudaFuncSetAttribute(shiftconv_gemm,
                         cudaFuncAttributeMaxDynamicSharedMemorySize, SMEM_TOTAL);

    prepass_kernel<<<256 + 784 * 8, 256>>>(x, Wm);
    dim3 grid(392, 4);
    shiftconv_gemm<<<grid, 256, SMEM_TOTAL>>>(gamma, beta, rmean, rvar, out);
}

// round 17
// speedup vs baseline: 1.2699x; 1.2699x over previous
#include <cuda_runtime.h>
#include <cuda_fp16.h>
#include <cstdint>

// ShiftConv: shift -> 1x1 conv (GEMM M=50176,N=512,K=512) -> BN -> ReLU.
// Round 17: revert R16's __ldcs (evict-first broke sector reuse at the roll
// boundaries -> prepass doubled). Exactly R15 plus ONLY the vectorized W
// convert (256 blocks, float4 in / uint2 out). GEMM byte-identical to
// R12/R15 (83us mma.sync plateau; tcgen05 blocked by sm_103 PTX target).

#define HDIM 28
#define HW   784
#define CCH  512
#define EPSV 1e-5f

#define MMA_F16(C, A, B) \
  asm volatile("mma.sync.aligned.m16n8k16.row.col.f32.f16.f16.f32 " \
    "{%0,%1,%2,%3}, {%4,%5,%6,%7}, {%8,%9}, {%0,%1,%2,%3};" \
    : "+f"((C)[0]), "+f"((C)[1]), "+f"((C)[2]), "+f"((C)[3]) \
    : "r"((A)[0]), "r"((A)[1]), "r"((A)[2]), "r"((A)[3]), \
      "r"((B)[0]), "r"((B)[1]))

#define LDSM4(R0, R1, R2, R3, addr) \
  asm volatile("ldmatrix.sync.aligned.m8n8.x4.shared.b16 {%0,%1,%2,%3}, [%4];" \
    : "=r"(R0), "=r"(R1), "=r"(R2), "=r"(R3) : "r"(addr))

#define CP16(dst, src) \
  asm volatile("cp.async.cg.shared.global [%0], [%1], 16;" :: "r"(dst), "l"(src))
#define CPCOMMIT() asm volatile("cp.async.commit_group;" ::: "memory")
#define CPWAIT(n)  asm volatile("cp.async.wait_group %0;" :: "n"(n) : "memory")

// K-chunk 64; smem row stride 64 real + 8 pad fp16 (144B, 16B aligned)
#define KC  64
#define KST 72
#define NSTAGE 3
#define MAT_BYTES (128 * KST * 2)          // 18432
#define A_OFF 0
#define B_OFF MAT_BYTES
#define STAGE_BYTES (2 * MAT_BYTES)        // 36864
#define SMEM_TOTAL (NSTAGE * STAGE_BYTES)  // 110592

__device__ __half g_Wh[CCH * CCH];
__device__ __half g_Ah[(size_t)50176 * CCH];   // shifted x, fp16, [p][c]

__device__ __forceinline__ uint32_t smem_u32(const void* p) {
    uint32_t a;
    asm("{ .reg .u64 t; cvta.to.shared.u64 t, %1; cvt.u32.u64 %0, t; }"
        : "=r"(a) : "l"(p));
    return a;
}

// Merged prepass. Blocks [0,256): W fp32->fp16 convert (float4 / uint2).
// Blocks [256, 256+784*8): shift-gather + transpose + fp16 convert of x.
__global__ __launch_bounds__(256)
void prepass_kernel(const float* __restrict__ x, const float* __restrict__ Wm) {
    __shared__ float tile[64][65];
    __shared__ int soff[64];
    const int tid = threadIdx.x;
    const int bid = blockIdx.x;

    if (bid < 256) {
        int i = (bid * 256 + tid) * 4;
        float4 v = *(const float4*)&Wm[i];
        __half2 h0 = __floats2half2_rn(v.x, v.y);
        __half2 h1 = __floats2half2_rn(v.z, v.w);
        *(uint2*)&g_Wh[i] = make_uint2(*(uint32_t*)&h0, *(uint32_t*)&h1);
        return;
    }

    const int b2 = bid - 256;
    const int p0 = (b2 >> 3) * 64;
    const int c0 = (b2 & 7) * 64;
    const int g  = c0 >> 7;

    if (tid < 64) {
        int pg = p0 + tid;
        int b  = pg / HW;
        int hw = pg - b * HW;
        int h  = hw / HDIM;
        int w  = hw - h * HDIM;
        int hs = h, ws = w;
        if      (g == 0) hs = (h + 1) % HDIM;
        else if (g == 1) hs = (h + HDIM - 1) % HDIM;
        else if (g == 2) ws = (w + 1) % HDIM;
        else             ws = (w + HDIM - 1) % HDIM;
        soff[tid] = b * (CCH * HW) + hs * HDIM + ws;
    }
    __syncthreads();
    #pragma unroll
    for (int it = 0; it < 16; it++) {       // read coalesced over p
        int lin = tid + it * 256;
        int c = lin >> 6, p = lin & 63;
        tile[c][p] = x[(size_t)(c0 + c) * HW + soff[p]];
    }
    __syncthreads();
    // write phase: one 8-channel octet per thread per iter, STG.128;
    // warp lanes span 8 octets x 4 p -> 4 fully-coalesced 128B lines.
    #pragma unroll
    for (int it = 0; it < 2; it++) {
        int lin = tid + it * 256;           // 0..511
        int oct = lin & 7;
        int p   = lin >> 3;
        int c   = oct * 8;
        uint32_t pk[4];
        #pragma unroll
        for (int j = 0; j < 4; j++) {
            __half2 h2 = __floats2half2_rn(tile[c + 2 * j][p],
                                           tile[c + 2 * j + 1][p]);
            pk[j] = *(uint32_t*)&h2;
        }
        *(uint4*)&g_Ah[(size_t)(p0 + p) * CCH + c0 + c] =
            make_uint4(pk[0], pk[1], pk[2], pk[3]);
    }
}

__global__ __launch_bounds__(256, 2)
void shiftconv_gemm(const float* __restrict__ gamma,
                    const float* __restrict__ beta,
                    const float* __restrict__ rmean,
                    const float* __restrict__ rvar,
                    float* __restrict__ out)
{
    extern __shared__ char dsm[];
    __shared__ float ssc[128], ssh[128];

    const int tid  = threadIdx.x;
    const int lane = tid & 31;
    const int wid  = tid >> 5;
    const int wm   = wid & 3;
    const int wn   = wid >> 2;
    const int g8   = lane >> 2;
    const int tig2 = (lane & 3) * 2;
    const int q    = lane >> 3;        // ldmatrix quad
    const int r8   = lane & 7;         // ldmatrix row within matrix

    const int pblock = blockIdx.x * 128;
    const int oblock = blockIdx.y * 128;

    if (tid < 128) {
        int o = oblock + tid;
        float sc = gamma[o] * rsqrtf(rvar[o] + EPSV);
        ssc[tid] = sc;
        ssh[tid] = beta[o] - rmean[o] * sc;
    }

    const uint32_t sdyn = smem_u32(dsm);

    uint32_t aoff[2];
    #pragma unroll
    for (int mt = 0; mt < 2; mt++)
        aoff[mt] = (uint32_t)(((wm * 32 + mt * 16 + (q & 1) * 8 + r8) * KST
                               + (q >> 1) * 8) * 2) + A_OFF;
    uint32_t boff[4];
    #pragma unroll
    for (int np = 0; np < 4; np++)
        boff[np] = (uint32_t)(((wn * 64 + np * 16 + (q >> 1) * 8 + r8) * KST
                               + (q & 1) * 8) * 2) + B_OFF;

    auto load_stage = [&](int ch) {
        int kc = ch * KC;
        uint32_t st = sdyn + (ch % NSTAGE) * STAGE_BYTES;
        #pragma unroll
        for (int it = 0; it < 4; it++) {
            int lin = tid + it * 256;
            int r = lin >> 3;
            int j = lin & 7;
            uint32_t d = st + r * (KST * 2) + j * 16;
            CP16(d + A_OFF, &g_Ah[(size_t)(pblock + r) * CCH + kc + j * 8]);
            CP16(d + B_OFF, &g_Wh[(size_t)(oblock + r) * CCH + kc + j * 8]);
        }
        CPCOMMIT();
    };

    float acc[2][8][4];
    #pragma unroll
    for (int mt = 0; mt < 2; mt++)
        #pragma unroll
        for (int nt = 0; nt < 8; nt++)
            #pragma unroll
            for (int rr = 0; rr < 4; rr++) acc[mt][nt][rr] = 0.0f;

    load_stage(0);
    load_stage(1);

    #pragma unroll
    for (int ch = 0; ch < 8; ch++) {
        if (ch < 7) CPWAIT(1);
        else        CPWAIT(0);
        __syncthreads();   // compute(ch-1) fully done -> buffer (ch-1)%3 free

        if (ch < 6) load_stage(ch + 2);   // writes buffer (ch+2)%3 == (ch-1)%3

        const uint32_t st = sdyn + (ch % NSTAGE) * STAGE_BYTES;
        #pragma unroll
        for (int kk = 0; kk < KC; kk += 16) {
            const uint32_t kb = st + kk * 2;
            uint32_t ah[2][4];
            uint32_t bh[8][2];
            LDSM4(ah[0][0], ah[0][1], ah[0][2], ah[0][3], kb + aoff[0]);
            LDSM4(ah[1][0], ah[1][1], ah[1][2], ah[1][3], kb + aoff[1]);
            LDSM4(bh[0][0], bh[0][1], bh[1][0], bh[1][1], kb + boff[0]);
            LDSM4(bh[2][0], bh[2][1], bh[3][0], bh[3][1], kb + boff[1]);

            MMA_F16(acc[0][0], ah[0], bh[0]);
            MMA_F16(acc[1][0], ah[1], bh[0]);
            MMA_F16(acc[0][1], ah[0], bh[1]);
            MMA_F16(acc[1][1], ah[1], bh[1]);
            LDSM4(bh[4][0], bh[4][1], bh[5][0], bh[5][1], kb + boff[2]);
            MMA_F16(acc[0][2], ah[0], bh[2]);
            MMA_F16(acc[1][2], ah[1], bh[2]);
            MMA_F16(acc[0][3], ah[0], bh[3]);
            MMA_F16(acc[1][3], ah[1], bh[3]);
            LDSM4(bh[6][0], bh[6][1], bh[7][0], bh[7][1], kb + boff[3]);
            MMA_F16(acc[0][4], ah[0], bh[4]);
            MMA_F16(acc[1][4], ah[1], bh[4]);
            MMA_F16(acc[0][5], ah[0], bh[5]);
            MMA_F16(acc[1][5], ah[1], bh[5]);
            MMA_F16(acc[0][6], ah[0], bh[6]);
            MMA_F16(acc[1][6], ah[1], bh[6]);
            MMA_F16(acc[0][7], ah[0], bh[7]);
            MMA_F16(acc[1][7], ah[1], bh[7]);
        }
    }

    // Epilogue: BN + ReLU.
    #pragma unroll
    for (int mt = 0; mt < 2; mt++) {
        int p0 = pblock + wm * 32 + mt * 16 + g8;
        int p1 = p0 + 8;
        int b0 = p0 / HW, hw0 = p0 - b0 * HW;
        int b1 = p1 / HW, hw1 = p1 - b1 * HW;
        #pragma unroll
        for (int nt = 0; nt < 8; nt++) {
            int oo  = wn * 64 + nt * 8 + tig2;
            float sc0 = ssc[oo],     sh0 = ssh[oo];
            float sc1 = ssc[oo + 1], sh1 = ssh[oo + 1];
            int o0 = oblock + oo;
            float* q00 = out + ((size_t)(b0 * CCH + o0)) * HW + hw0;
            float* q01 = out + ((size_t)(b0 * CCH + o0 + 1)) * HW + hw0;
            float* q10 = out + ((size_t)(b1 * CCH + o0)) * HW + hw1;
            float* q11 = out + ((size_t)(b1 * CCH + o0 + 1)) * HW + hw1;
            *q00 = fmaxf(fmaf(acc[mt][nt][0], sc0, sh0), 0.0f);
            *q01 = fmaxf(fmaf(acc[mt][nt][1], sc1, sh1), 0.0f);
            *q10 = fmaxf(fmaf(acc[mt][nt][2], sc0, sh0), 0.0f);
            *q11 = fmaxf(fmaf(acc[mt][nt][3], sc1, sh1), 0.0f);
        }
    }
}

extern "C" void kernel_launch(void* const* d_in, const int* in_sizes, int n_in,
                              void* d_out, int out_size)
{
    const float* x     = (const float*)d_in[0];
    const float* Wm    = (const float*)d_in[1];
    const float* gamma = (const float*)d_in[2];
    const float* beta  = (const float*)d_in[3];
    const float* rmean = (const float*)d_in[4];
    const float* rvar  = (const float*)d_in[5];
    float* out = (float*)d_out;

    cudaFuncSetAttribute(shiftconv_gemm,
                         cudaFuncAttributeMaxDynamicSharedMemorySize, SMEM_TOTAL);

    prepass_kernel<<<256 + 784 * 8, 256>>>(x, Wm);
    dim3 grid(392, 4);
    shiftconv_gemm<<<grid, 256, SMEM_TOTAL>>>(gamma, beta, rmean, rvar, out);
}